// round 7
// baseline (speedup 1.0000x reference)
#include <cuda_runtime.h>

#define NT    512
#define TT    512
#define ROWP  68        // padded row stride (floats) for 16x64 tiles
#define CHFL  9632      // floats per chain's smem slab
// slab layout (floats): W:4096 | xq:2*1088 | xk:2*1088 | gz:1088 | bb:64 | eta:32

#define BARSYNC(id) asm volatile("bar.sync %0, 256;" :: "r"(id) : "memory")

__global__ __launch_bounds__(NT, 1)
void ttt_kernel(const float* __restrict__ XQ, const float* __restrict__ XK,
                const float* __restrict__ XV, const float* __restrict__ W1,
                const float* __restrict__ b1, const float* __restrict__ gam,
                const float* __restrict__ bet, float* __restrict__ out)
{
    extern __shared__ float smem[];

    const int tid  = threadIdx.x;
    const int half = tid >> 8;            // 0 or 1: which chain
    const int ctid = tid & 255;           // thread id within chain
    const int bid  = half + 1;            // named barrier id (1 or 2)
    const int bh   = blockIdx.x * 2 + half;
    const int h    = bh & 15;
    const int k    = ctid >> 4;           // token row 0..15
    const int q    = ctid & 15;
    const int f0   = q << 2;              // 4 features per thread

    float* const W     = smem + half*CHFL;
    float* const xq_s0 = W + 4096;
    float* const xq_s1 = xq_s0 + 16*ROWP;
    float* const xk_s0 = xq_s1 + 16*ROWP;
    float* const xk_s1 = xk_s0 + 16*ROWP;
    float* const gz_s  = xk_s1 + 16*ROWP;
    float* const bb    = gz_s + 16*ROWP;
    float* const eta0  = bb + 64;
    float* const eta1  = eta0 + 16;

    const size_t base = (size_t)bh * (TT * 1024);
    const float* xqg = XQ + base;
    const float* xkg = XK + base;
    const float* xvg = XV + base;
    float*       og  = out + base;

    // ---- init carried state ----
    {
        const float* Wg = W1 + (size_t)h * 4096;
        #pragma unroll
        for (int i = 0; i < 4; i++)
            *(float4*)&W[i*1024 + ctid*4] = *(const float4*)&Wg[i*1024 + ctid*4];
        if (ctid < 16)
            *(float4*)&bb[ctid*4] = *(const float4*)&b1[h*64 + ctid*4];
    }
    const float4 g4  = *(const float4*)&gam[h*64 + f0];
    const float4 be4 = *(const float4*)&bet[h*64 + f0];

    // ---- stage step 0 tiles + eta0 into buffer 0 ----
    float4 q4 = *(const float4*)&xqg[ctid*4];
    float4 k4 = *(const float4*)&xkg[ctid*4];
    float4 v4 = *(const float4*)&xvg[ctid*4];
    *(float4*)&xq_s0[k*ROWP + f0] = q4;
    *(float4*)&xk_s0[k*ROWP + f0] = k4;
    {
        float ss = k4.x*k4.x + k4.y*k4.y + k4.z*k4.z + k4.w*k4.w;
        #pragma unroll
        for (int m = 8; m >= 1; m >>= 1) ss += __shfl_xor_sync(~0u, ss, m, 16);
        if (q == 0) eta0[k] = 0.01f / (1.0f + fmaxf(sqrtf(ss), 1e-6f));
    }
    BARSYNC(bid);

    int p = 0;
    for (int t = 0; t < TT; t++) {
        const float* xqp = p ? xq_s1 : xq_s0;
        const float* xkp = p ? xk_s1 : xk_s0;
        const float* etp = p ? eta1  : eta0;

        // ---- prefetch next step's tiles early (hide DRAM) ----
        float4 nq4 = make_float4(0.f,0.f,0.f,0.f), nk4 = nq4, nv4 = nq4;
        if (t + 1 < TT) {
            const size_t off = (size_t)(t+1)*1024 + ctid*4;
            nq4 = *(const float4*)&xqg[off];
            nk4 = *(const float4*)&xkg[off];
            nv4 = *(const float4*)&xvg[off];
        }

        // em = mean(eta), el = eta[15] (precomputed last step)
        float em, el;
        {
            const float4 e0 = *(const float4*)&etp[0];
            const float4 e1 = *(const float4*)&etp[4];
            const float4 e2 = *(const float4*)&etp[8];
            const float4 e3 = *(const float4*)&etp[12];
            em = ((e0.x+e0.y+e0.z+e0.w) + (e1.x+e1.y+e1.z+e1.w)
                + (e2.x+e2.y+e2.z+e2.w) + (e3.x+e3.y+e3.z+e3.w)) * (1.0f/16.0f);
            el = e3.w;
        }

        // ---- fused: z=xk@W+b, zd=xq@W+b, a=xq[k].xk[q]+1 ----
        float4 z  = *(const float4*)&bb[f0];
        float4 zd = z;
        float  a  = 1.0f;
        #pragma unroll 4
        for (int j = 0; j < 16; j++) {
            const int d0 = j << 2;
            const float4 xk4 = *(const float4*)&xkp[k*ROWP + d0];
            const float4 xq4 = *(const float4*)&xqp[k*ROWP + d0];
            const float4 xkA = *(const float4*)&xkp[q*ROWP + d0];
            a = fmaf(xq4.x, xkA.x, a);
            a = fmaf(xq4.y, xkA.y, a);
            a = fmaf(xq4.z, xkA.z, a);
            a = fmaf(xq4.w, xkA.w, a);
            {
                const float4 w = *(const float4*)&W[(d0+0)*64 + f0];
                z.x  = fmaf(xk4.x, w.x, z.x);  z.y  = fmaf(xk4.x, w.y, z.y);
                z.z  = fmaf(xk4.x, w.z, z.z);  z.w  = fmaf(xk4.x, w.w, z.w);
                zd.x = fmaf(xq4.x, w.x, zd.x); zd.y = fmaf(xq4.x, w.y, zd.y);
                zd.z = fmaf(xq4.x, w.z, zd.z); zd.w = fmaf(xq4.x, w.w, zd.w);
            }
            {
                const float4 w = *(const float4*)&W[(d0+1)*64 + f0];
                z.x  = fmaf(xk4.y, w.x, z.x);  z.y  = fmaf(xk4.y, w.y, z.y);
                z.z  = fmaf(xk4.y, w.z, z.z);  z.w  = fmaf(xk4.y, w.w, z.w);
                zd.x = fmaf(xq4.y, w.x, zd.x); zd.y = fmaf(xq4.y, w.y, zd.y);
                zd.z = fmaf(xq4.y, w.z, zd.z); zd.w = fmaf(xq4.y, w.w, zd.w);
            }
            {
                const float4 w = *(const float4*)&W[(d0+2)*64 + f0];
                z.x  = fmaf(xk4.z, w.x, z.x);  z.y  = fmaf(xk4.z, w.y, z.y);
                z.z  = fmaf(xk4.z, w.z, z.z);  z.w  = fmaf(xk4.z, w.w, z.w);
                zd.x = fmaf(xq4.z, w.x, zd.x); zd.y = fmaf(xq4.z, w.y, zd.y);
                zd.z = fmaf(xq4.z, w.z, zd.z); zd.w = fmaf(xq4.z, w.w, zd.w);
            }
            {
                const float4 w = *(const float4*)&W[(d0+3)*64 + f0];
                z.x  = fmaf(xk4.w, w.x, z.x);  z.y  = fmaf(xk4.w, w.y, z.y);
                z.z  = fmaf(xk4.w, w.z, z.z);  z.w  = fmaf(xk4.w, w.w, z.w);
                zd.x = fmaf(xq4.w, w.x, zd.x); zd.y = fmaf(xq4.w, w.y, zd.y);
                zd.z = fmaf(xq4.w, w.z, zd.z); zd.w = fmaf(xq4.w, w.w, zd.w);
            }
        }

        // ---- LN(z) single-pass -> grad_Z1 ----
        float s1 = z.x + z.y + z.z + z.w;
        float s2 = z.x*z.x + z.y*z.y + z.z*z.z + z.w*z.w;
        #pragma unroll
        for (int m = 8; m >= 1; m >>= 1) {
            s1 += __shfl_xor_sync(~0u, s1, m, 16);
            s2 += __shfl_xor_sync(~0u, s2, m, 16);
        }
        const float mu  = s1 * 0.015625f;
        const float var = fmaf(-mu, mu, s2 * 0.015625f);
        const float r   = rsqrtf(var + 1e-6f);
        float4 gz;
        gz.x = 2.0f * (fmaf(g4.x, (z.x-mu)*r, be4.x) - v4.x + k4.x);
        gz.y = 2.0f * (fmaf(g4.y, (z.y-mu)*r, be4.y) - v4.y + k4.y);
        gz.z = 2.0f * (fmaf(g4.z, (z.z-mu)*r, be4.z) - v4.z + k4.z);
        gz.w = 2.0f * (fmaf(g4.w, (z.w-mu)*r, be4.w) - v4.w + k4.w);
        *(float4*)&gz_s[k*ROWP + f0] = gz;
        BARSYNC(bid);                                      // S2

        // ---- carry update: rank-1, in place ----
        {
            const float4 gl = *(const float4*)&gz_s[15*ROWP + f0];
            #pragma unroll
            for (int j = 0; j < 4; j++) {
                const int d = k + 16*j;
                const float cf = -el * xkp[15*ROWP + d];
                float4 w4 = *(float4*)&W[d*64 + f0];
                w4.x = fmaf(cf, gl.x, w4.x); w4.y = fmaf(cf, gl.y, w4.y);
                w4.z = fmaf(cf, gl.z, w4.z); w4.w = fmaf(cf, gl.w, w4.w);
                *(float4*)&W[d*64 + f0] = w4;
            }
            if (ctid < 16) {   // k==0, f0 == ctid*4, gl == gz_s[15][f0]
                float4 bv = *(float4*)&bb[f0];
                bv.x = fmaf(-el, gl.x, bv.x); bv.y = fmaf(-el, gl.y, bv.y);
                bv.z = fmaf(-el, gl.z, bv.z); bv.w = fmaf(-el, gl.w, bv.w);
                *(float4*)&bb[f0] = bv;
            }
        }

        // ---- correction: zd -= em * (A' @ gz), A' via half-warp shfl ----
        float4 c = make_float4(0.f,0.f,0.f,0.f);
        #pragma unroll
        for (int kp2 = 0; kp2 < 16; kp2++) {
            const float av  = __shfl_sync(~0u, a, kp2, 16);
            const float4 gv = *(const float4*)&gz_s[kp2*ROWP + f0];
            c.x = fmaf(av, gv.x, c.x); c.y = fmaf(av, gv.y, c.y);
            c.z = fmaf(av, gv.z, c.z); c.w = fmaf(av, gv.w, c.w);
        }
        zd.x = fmaf(-em, c.x, zd.x); zd.y = fmaf(-em, c.y, zd.y);
        zd.z = fmaf(-em, c.z, zd.z); zd.w = fmaf(-em, c.w, zd.w);

        // ---- LN(zd) single-pass, out = xq + ln ----
        float t1 = zd.x + zd.y + zd.z + zd.w;
        float t2 = zd.x*zd.x + zd.y*zd.y + zd.z*zd.z + zd.w*zd.w;
        #pragma unroll
        for (int m = 8; m >= 1; m >>= 1) {
            t1 += __shfl_xor_sync(~0u, t1, m, 16);
            t2 += __shfl_xor_sync(~0u, t2, m, 16);
        }
        const float mu2  = t1 * 0.015625f;
        const float var2 = fmaf(-mu2, mu2, t2 * 0.015625f);
        const float r2   = rsqrtf(var2 + 1e-6f);
        float4 o;
        o.x = q4.x + fmaf(g4.x, (zd.x-mu2)*r2, be4.x);
        o.y = q4.y + fmaf(g4.y, (zd.y-mu2)*r2, be4.y);
        o.z = q4.z + fmaf(g4.z, (zd.z-mu2)*r2, be4.z);
        o.w = q4.w + fmaf(g4.w, (zd.w-mu2)*r2, be4.w);
        *(float4*)&og[(size_t)t*1024 + ctid*4] = o;

        // ---- stage NEXT step's tiles + eta into other buffer ----
        {
            float* const xqn = p ? xq_s0 : xq_s1;
            float* const xkn = p ? xk_s0 : xk_s1;
            float* const etn = p ? eta0  : eta1;
            *(float4*)&xqn[k*ROWP + f0] = nq4;
            *(float4*)&xkn[k*ROWP + f0] = nk4;
            float ss = nk4.x*nk4.x + nk4.y*nk4.y + nk4.z*nk4.z + nk4.w*nk4.w;
            #pragma unroll
            for (int m = 8; m >= 1; m >>= 1) ss += __shfl_xor_sync(~0u, ss, m, 16);
            if (q == 0) etn[k] = 0.01f / (1.0f + fmaxf(sqrtf(ss), 1e-6f));
        }
        BARSYNC(bid);                                      // S3

        q4 = nq4; k4 = nk4; v4 = nv4; p ^= 1;
    }
}

extern "C" void kernel_launch(void* const* d_in, const int* in_sizes, int n_in,
                              void* d_out, int out_size) {
    const float* XQ  = (const float*)d_in[0];
    const float* XK  = (const float*)d_in[1];
    const float* XV  = (const float*)d_in[2];
    const float* W1  = (const float*)d_in[3];
    const float* b1  = (const float*)d_in[4];
    const float* gam = (const float*)d_in[5];
    const float* bet = (const float*)d_in[6];
    float* out = (float*)d_out;

    const int nbh  = in_sizes[0] / (TT * 16 * 64);   // B*H = 64
    const int smem = 2 * CHFL * sizeof(float);       // ~77 KB
    static int configured = 0;
    if (!configured) {
        cudaFuncSetAttribute(ttt_kernel, cudaFuncAttributeMaxDynamicSharedMemorySize, smem);
        configured = 1;
    }
    ttt_kernel<<<nbh / 2, NT, smem>>>(XQ, XK, XV, W1, b1, gam, bet, out);
}

// round 8
// speedup vs baseline: 1.7389x; 1.7389x over previous
#include <cuda_runtime.h>

#define NT   512
#define TT   512
#define ROWP 68

// dynamic smem layout (float offsets)
#define OFF_XQ   4096                 // 2 buffers x 1088
#define OFF_XK   (4096+2176)
#define OFF_GZ   (4096+4352)          // 1088
#define OFF_PZ   (OFF_GZ+1088)        // 2048 = [h][ctid][4]
#define OFF_PZD  (OFF_PZ+2048)        // 2048
#define OFF_PA   (OFF_PZD+2048)       // 512
#define OFF_BB   (OFF_PA+512)         // 64
#define OFF_ETA  (OFF_BB+64)          // 2 x 16
#define SMF      (OFF_ETA+32)

__global__ __launch_bounds__(NT, 1)
void ttt_kernel(const float* __restrict__ XQ, const float* __restrict__ XK,
                const float* __restrict__ XV, const float* __restrict__ W1,
                const float* __restrict__ b1, const float* __restrict__ gam,
                const float* __restrict__ bet, float* __restrict__ out)
{
    extern __shared__ float sm[];
    float* const W  = sm;
    float* const GZ = sm + OFF_GZ;
    float* const BB = sm + OFF_BB;

    const int tid  = threadIdx.x;
    const int h    = tid >> 8;          // d-half: 0 or 1
    const int ctid = tid & 255;
    const int k    = ctid >> 4;         // token row 0..15
    const int q    = ctid & 15;
    const int f0   = q << 2;            // 4 features per thread
    const int bh   = blockIdx.x;
    const int hh   = bh & 15;

    const size_t base = (size_t)bh * (TT * 1024);
    const float* xqg = XQ + base;
    const float* xkg = XK + base;
    const float* xvg = XV + base;
    float*       og  = out + base;

    // ---- init carried state ----
    {
        const float* Wg = W1 + (size_t)hh * 4096;
        *(float4*)&W[tid*8]     = *(const float4*)&Wg[tid*8];
        *(float4*)&W[tid*8 + 4] = *(const float4*)&Wg[tid*8 + 4];
        if (tid < 16)
            *(float4*)&BB[tid*4] = *(const float4*)&b1[hh*64 + tid*4];
    }
    const float4 g4  = *(const float4*)&gam[hh*64 + f0];
    const float4 be4 = *(const float4*)&bet[hh*64 + f0];

    // ---- stage step-0 tiles + eta0 ----
    float4 q4 = *(const float4*)&xqg[ctid*4];
    float4 k4 = *(const float4*)&xkg[ctid*4];
    float4 v4 = *(const float4*)&xvg[ctid*4];
    if (h == 1) {
        *(float4*)&sm[OFF_XQ + k*ROWP + f0] = q4;
        *(float4*)&sm[OFF_XK + k*ROWP + f0] = k4;
        float ss = k4.x*k4.x + k4.y*k4.y + k4.z*k4.z + k4.w*k4.w;
        #pragma unroll
        for (int m = 8; m >= 1; m >>= 1) ss += __shfl_xor_sync(~0u, ss, m, 16);
        if (q == 0) sm[OFF_ETA + k] = 0.01f / (1.0f + fmaxf(sqrtf(ss), 1e-6f));
    }
    __syncthreads();

    int p = 0;
    for (int t = 0; t < TT; t++) {
        const float* xqp = sm + OFF_XQ + p*1088;
        const float* xkp = sm + OFF_XK + p*1088;

        // ---- prefetch next step (both halves; hides DRAM under main loop) ----
        float4 nq4 = make_float4(0.f,0.f,0.f,0.f), nk4 = nq4, nv4 = nq4;
        if (t + 1 < TT) {
            const size_t off = (size_t)(t+1)*1024 + ctid*4;
            nq4 = *(const float4*)&xqg[off];
            nk4 = *(const float4*)&xkg[off];
            if (h == 0) nv4 = *(const float4*)&xvg[off];
        }

        // ---- main half-loop: z/zd/a partials over d in [32h, 32h+32) ----
        float4 z, zd; float a;
        if (h == 0) { z = *(const float4*)&BB[f0]; a = 1.0f; }
        else        { z = make_float4(0.f,0.f,0.f,0.f); a = 0.0f; }
        zd = z;
        const int db = h << 5;
        #pragma unroll
        for (int j = 0; j < 8; j++) {
            const int d0 = db + (j << 2);
            const float4 xk4 = *(const float4*)&xkp[k*ROWP + d0];
            const float4 xq4 = *(const float4*)&xqp[k*ROWP + d0];
            const float4 xkA = *(const float4*)&xkp[q*ROWP + d0];
            a = fmaf(xq4.x, xkA.x, a);
            a = fmaf(xq4.y, xkA.y, a);
            a = fmaf(xq4.z, xkA.z, a);
            a = fmaf(xq4.w, xkA.w, a);
            {
                const float4 w = *(const float4*)&W[(d0+0)*64 + f0];
                z.x  = fmaf(xk4.x, w.x, z.x);  z.y  = fmaf(xk4.x, w.y, z.y);
                z.z  = fmaf(xk4.x, w.z, z.z);  z.w  = fmaf(xk4.x, w.w, z.w);
                zd.x = fmaf(xq4.x, w.x, zd.x); zd.y = fmaf(xq4.x, w.y, zd.y);
                zd.z = fmaf(xq4.x, w.z, zd.z); zd.w = fmaf(xq4.x, w.w, zd.w);
            }
            {
                const float4 w = *(const float4*)&W[(d0+1)*64 + f0];
                z.x  = fmaf(xk4.y, w.x, z.x);  z.y  = fmaf(xk4.y, w.y, z.y);
                z.z  = fmaf(xk4.y, w.z, z.z);  z.w  = fmaf(xk4.y, w.w, z.w);
                zd.x = fmaf(xq4.y, w.x, zd.x); zd.y = fmaf(xq4.y, w.y, zd.y);
                zd.z = fmaf(xq4.y, w.z, zd.z); zd.w = fmaf(xq4.y, w.w, zd.w);
            }
            {
                const float4 w = *(const float4*)&W[(d0+2)*64 + f0];
                z.x  = fmaf(xk4.z, w.x, z.x);  z.y  = fmaf(xk4.z, w.y, z.y);
                z.z  = fmaf(xk4.z, w.z, z.z);  z.w  = fmaf(xk4.z, w.w, z.w);
                zd.x = fmaf(xq4.z, w.x, zd.x); zd.y = fmaf(xq4.z, w.y, zd.y);
                zd.z = fmaf(xq4.z, w.z, zd.z); zd.w = fmaf(xq4.z, w.w, zd.w);
            }
            {
                const float4 w = *(const float4*)&W[(d0+3)*64 + f0];
                z.x  = fmaf(xk4.w, w.x, z.x);  z.y  = fmaf(xk4.w, w.y, z.y);
                z.z  = fmaf(xk4.w, w.z, z.z);  z.w  = fmaf(xk4.w, w.w, z.w);
                zd.x = fmaf(xq4.w, w.x, zd.x); zd.y = fmaf(xq4.w, w.y, zd.y);
                zd.z = fmaf(xq4.w, w.z, zd.z); zd.w = fmaf(xq4.w, w.w, zd.w);
            }
        }

        // ---- h=1: stage next tiles + eta (overlaps h=0's later LN work) ----
        if (h == 1) {
            float* xqn = sm + OFF_XQ + (p^1)*1088;
            float* xkn = sm + OFF_XK + (p^1)*1088;
            *(float4*)&xqn[k*ROWP + f0] = nq4;
            *(float4*)&xkn[k*ROWP + f0] = nk4;
            float ss = nk4.x*nk4.x + nk4.y*nk4.y + nk4.z*nk4.z + nk4.w*nk4.w;
            #pragma unroll
            for (int m = 8; m >= 1; m >>= 1) ss += __shfl_xor_sync(~0u, ss, m, 16);
            if (q == 0) sm[OFF_ETA + (p^1)*16 + k] = 0.01f / (1.0f + fmaxf(sqrtf(ss), 1e-6f));
        }

        // ---- exchange partials ----
        *(float4*)&sm[OFF_PZ  + h*1024 + ctid*4] = z;
        *(float4*)&sm[OFF_PZD + h*1024 + ctid*4] = zd;
        sm[OFF_PA + h*256 + ctid] = a;
        __syncthreads();                                   // S_a

        if (h == 0) {
            // combine halves
            const float4 z2  = *(const float4*)&sm[OFF_PZ  + 1024 + ctid*4];
            const float4 zd2 = *(const float4*)&sm[OFF_PZD + 1024 + ctid*4];
            a += sm[OFF_PA + 256 + ctid];
            z.x += z2.x;  z.y += z2.y;  z.z += z2.z;  z.w += z2.w;
            zd.x += zd2.x; zd.y += zd2.y; zd.z += zd2.z; zd.w += zd2.w;

            // LN(z) single-pass -> grad_Z1
            float s1 = z.x + z.y + z.z + z.w;
            float s2 = z.x*z.x + z.y*z.y + z.z*z.z + z.w*z.w;
            #pragma unroll
            for (int m = 8; m >= 1; m >>= 1) {
                s1 += __shfl_xor_sync(~0u, s1, m, 16);
                s2 += __shfl_xor_sync(~0u, s2, m, 16);
            }
            const float mu  = s1 * 0.015625f;
            const float var = fmaf(-mu, mu, s2 * 0.015625f);
            const float r   = rsqrtf(var + 1e-6f);
            float4 gz;
            gz.x = 2.0f * (fmaf(g4.x, (z.x-mu)*r, be4.x) - v4.x + k4.x);
            gz.y = 2.0f * (fmaf(g4.y, (z.y-mu)*r, be4.y) - v4.y + k4.y);
            gz.z = 2.0f * (fmaf(g4.z, (z.z-mu)*r, be4.z) - v4.z + k4.z);
            gz.w = 2.0f * (fmaf(g4.w, (z.w-mu)*r, be4.w) - v4.w + k4.w);
            *(float4*)&GZ[k*ROWP + f0] = gz;
        }
        __syncthreads();                                   // S2

        // em, el from current eta buffer
        float em, el;
        {
            const float4 e0 = *(const float4*)&sm[OFF_ETA + p*16 + 0];
            const float4 e1 = *(const float4*)&sm[OFF_ETA + p*16 + 4];
            const float4 e2 = *(const float4*)&sm[OFF_ETA + p*16 + 8];
            const float4 e3 = *(const float4*)&sm[OFF_ETA + p*16 + 12];
            em = ((e0.x+e0.y+e0.z+e0.w) + (e1.x+e1.y+e1.z+e1.w)
                + (e2.x+e2.y+e2.z+e2.w) + (e3.x+e3.y+e3.z+e3.w)) * (1.0f/16.0f);
            el = e3.w;
        }

        // ---- W rank-1 update, rows split across halves ----
        {
            const float4 gl = *(const float4*)&GZ[15*ROWP + f0];
            #pragma unroll
            for (int jj = 0; jj < 2; jj++) {
                const int d = k + 16*((h<<1) + jj);
                const float cf = -el * xkp[15*ROWP + d];
                float4 w4 = *(float4*)&W[d*64 + f0];
                w4.x = fmaf(cf, gl.x, w4.x); w4.y = fmaf(cf, gl.y, w4.y);
                w4.z = fmaf(cf, gl.z, w4.z); w4.w = fmaf(cf, gl.w, w4.w);
                *(float4*)&W[d*64 + f0] = w4;
            }
            if (h == 0 && ctid < 16) {     // k==0: f0 == ctid*4
                float4 bv = *(float4*)&BB[f0];
                bv.x = fmaf(-el, gl.x, bv.x); bv.y = fmaf(-el, gl.y, bv.y);
                bv.z = fmaf(-el, gl.z, bv.z); bv.w = fmaf(-el, gl.w, bv.w);
                *(float4*)&BB[f0] = bv;
            }
        }

        if (h == 0) {
            // correction: zd -= em * (A' @ gz); A' via half-warp shfl
            float4 c = make_float4(0.f,0.f,0.f,0.f);
            #pragma unroll
            for (int kp2 = 0; kp2 < 16; kp2++) {
                const float av  = __shfl_sync(~0u, a, kp2, 16);
                const float4 gv = *(const float4*)&GZ[kp2*ROWP + f0];
                c.x = fmaf(av, gv.x, c.x); c.y = fmaf(av, gv.y, c.y);
                c.z = fmaf(av, gv.z, c.z); c.w = fmaf(av, gv.w, c.w);
            }
            zd.x = fmaf(-em, c.x, zd.x); zd.y = fmaf(-em, c.y, zd.y);
            zd.z = fmaf(-em, c.z, zd.z); zd.w = fmaf(-em, c.w, zd.w);

            // LN(zd), out = xq + ln
            float t1 = zd.x + zd.y + zd.z + zd.w;
            float t2 = zd.x*zd.x + zd.y*zd.y + zd.z*zd.z + zd.w*zd.w;
            #pragma unroll
            for (int m = 8; m >= 1; m >>= 1) {
                t1 += __shfl_xor_sync(~0u, t1, m, 16);
                t2 += __shfl_xor_sync(~0u, t2, m, 16);
            }
            const float mu2  = t1 * 0.015625f;
            const float var2 = fmaf(-mu2, mu2, t2 * 0.015625f);
            const float r2   = rsqrtf(var2 + 1e-6f);
            float4 o;
            o.x = q4.x + fmaf(g4.x, (zd.x-mu2)*r2, be4.x);
            o.y = q4.y + fmaf(g4.y, (zd.y-mu2)*r2, be4.y);
            o.z = q4.z + fmaf(g4.z, (zd.z-mu2)*r2, be4.z);
            o.w = q4.w + fmaf(g4.w, (zd.w-mu2)*r2, be4.w);
            *(float4*)&og[(size_t)t*1024 + ctid*4] = o;
        }
        __syncthreads();                                   // S3

        q4 = nq4; k4 = nk4; v4 = nv4; p ^= 1;
    }
}

extern "C" void kernel_launch(void* const* d_in, const int* in_sizes, int n_in,
                              void* d_out, int out_size) {
    const float* XQ  = (const float*)d_in[0];
    const float* XK  = (const float*)d_in[1];
    const float* XV  = (const float*)d_in[2];
    const float* W1  = (const float*)d_in[3];
    const float* b1  = (const float*)d_in[4];
    const float* gam = (const float*)d_in[5];
    const float* bet = (const float*)d_in[6];
    float* out = (float*)d_out;

    const int nbh  = in_sizes[0] / (TT * 16 * 64);   // B*H = 64
    const int smem = SMF * (int)sizeof(float);       // ~57 KB
    static int configured = 0;
    if (!configured) {
        cudaFuncSetAttribute(ttt_kernel, cudaFuncAttributeMaxDynamicSharedMemorySize, smem);
        configured = 1;
    }
    ttt_kernel<<<nbh, NT, smem>>>(XQ, XK, XV, W1, b1, gam, bet, out);
}